// round 12
// baseline (speedup 1.0000x reference)
#include <cuda_runtime.h>
#include <cuda_bf16.h>
#include <cstdint>

#define N_NODES 100000
#define F1 128
#define F2 64
#define EMAX 1600000

// Scratch (device globals: allocation-free, graph-safe)
__device__ float g_bufA[N_NODES * F2];   // GEMM output (pre-aggregation messages)
__device__ float g_bufC[N_NODES * F2];   // hidden activations h1
__device__ float g_rso[N_NODES];         // rsqrt(deg_out)
__device__ float g_rsi[N_NODES];         // rsqrt(deg_in)
__device__ int   g_dego[N_NODES];
__device__ int   g_degi[N_NODES];
__device__ int   g_off[N_NODES];         // segment start per dst node
__device__ int   g_cur[N_NODES];         // fill cursor per dst node
__device__ int   g_sorted[EMAX];         // src indices grouped by dst
__device__ int   g_total;                // segment allocator

// ---------------------------------------------------------------------------
__global__ void k_zero() {
    int i = blockIdx.x * blockDim.x + threadIdx.x;
    if (i < N_NODES) { g_dego[i] = 0; g_degi[i] = 0; }
    if (i == 0) g_total = 0;
}

__global__ void k_degree(const int* __restrict__ src, const int* __restrict__ dst, int E) {
    int i = blockIdx.x * blockDim.x + threadIdx.x;
    if (i >= E) return;
    atomicAdd(&g_dego[src[i]], 1);
    atomicAdd(&g_degi[dst[i]], 1);
}

// Segment allocation (warp scan + 1 atomic/warp) fused with norm computation.
__global__ void k_alloc() {
    int i = blockIdx.x * blockDim.x + threadIdx.x;
    int lane = threadIdx.x & 31;
    int deg = 0, dego = 0;
    if (i < N_NODES) { deg = g_degi[i]; dego = g_dego[i]; }
    int incl = deg;
#pragma unroll
    for (int o = 1; o < 32; o <<= 1) {
        int n = __shfl_up_sync(0xFFFFFFFFu, incl, o);
        if (lane >= o) incl += n;
    }
    int wtotal = __shfl_sync(0xFFFFFFFFu, incl, 31);
    int base = 0;
    if (lane == 0) base = atomicAdd(&g_total, wtotal);
    base = __shfl_sync(0xFFFFFFFFu, base, 0);
    if (i < N_NODES) {
        int off = base + incl - deg;
        g_off[i] = off;
        g_cur[i] = off;
        g_rsi[i] = rsqrtf((float)max(deg, 1));
        g_rso[i] = rsqrtf((float)max(dego, 1));
    }
}

// Group src indices by dst (counting-sort placement).
__global__ void k_bin(const int* __restrict__ src, const int* __restrict__ dst, int E) {
    int e = blockIdx.x * blockDim.x + threadIdx.x;
    if (e >= E) return;
    int d = dst[e];
    int p = atomicAdd(&g_cur[d], 1);
    g_sorted[p] = src[e];
}

// ---------------------------------------------------------------------------
// Y[r, :] = (X[r, :] @ W) * g_rso[r]    X:[M,K]  W:[K,64]  Y:[M,64]
// 128 threads, tile 128 rows x 64 cols, 8x8 register blocking.
// Per thread-k4: 16 LDS.128 vs 256 FFMA -> FMA-bound (2x LDS headroom).
// X tile XOR-swizzled (c4 ^ (row>>3 & 7)) so the 4 ty-addresses per xv load
// hit distinct bank-quads; W loads at c4 = tx and tx+8 are conflict-free.
template <int K>
__global__ void __launch_bounds__(128, 2)
k_gemm_scale(const float* __restrict__ X, const float* __restrict__ W,
             float* __restrict__ Y, int M) {
    constexpr int C4 = K / 4;                 // float4 per X row
    extern __shared__ float4 sm4[];
    float4* sW = sm4;                         // [K][16] float4
    float4* sX = sm4 + K * 16;                // [128][C4] float4, swizzled

    const int tid = threadIdx.x;
    const int row0 = blockIdx.x * 128;

    // Load W (whole matrix, row-major [K][64])
    for (int i = tid; i < K * 16; i += 128)
        sW[i] = ((const float4*)W)[i];

    // Load X tile with swizzle (zero-fill out-of-range rows)
    for (int i = tid; i < 128 * C4; i += 128) {
        int r = i / C4, c4 = i % C4;
        float4 v = make_float4(0.f, 0.f, 0.f, 0.f);
        if (row0 + r < M)
            v = ((const float4*)(X + (size_t)(row0 + r) * K))[c4];
        sX[r * C4 + (c4 ^ ((r >> 3) & 7))] = v;
    }
    __syncthreads();

    const int tx = tid & 7;    // col group: cols {tx*4..+3, 32+tx*4..+3}
    const int ty = tid >> 3;   // row group: rows ty*8 .. ty*8+7

    float acc[8][8];
#pragma unroll
    for (int j = 0; j < 8; j++)
#pragma unroll
        for (int c = 0; c < 8; c++) acc[j][c] = 0.0f;

    const int swb = ty & 7;
    for (int k4 = 0; k4 < C4; ++k4) {
        float4 xv[8];
        const int sw = k4 ^ swb;
#pragma unroll
        for (int j = 0; j < 8; j++)
            xv[j] = sX[(ty * 8 + j) * C4 + sw];
#pragma unroll
        for (int kk = 0; kk < 4; kk++) {
            float4 w0 = sW[(k4 * 4 + kk) * 16 + tx];
            float4 w1 = sW[(k4 * 4 + kk) * 16 + tx + 8];
#pragma unroll
            for (int j = 0; j < 8; j++) {
                const float* xp = (const float*)&xv[j];
                float xs = xp[kk];
                acc[j][0] += xs * w0.x;
                acc[j][1] += xs * w0.y;
                acc[j][2] += xs * w0.z;
                acc[j][3] += xs * w0.w;
                acc[j][4] += xs * w1.x;
                acc[j][5] += xs * w1.y;
                acc[j][6] += xs * w1.z;
                acc[j][7] += xs * w1.w;
            }
        }
    }

#pragma unroll
    for (int j = 0; j < 8; j++) {
        int gr = row0 + ty * 8 + j;
        if (gr < M) {
            float s = g_rso[gr];
            float4* yr = (float4*)(Y + (size_t)gr * 64);
            yr[tx]     = make_float4(acc[j][0] * s, acc[j][1] * s, acc[j][2] * s, acc[j][3] * s);
            yr[tx + 8] = make_float4(acc[j][4] * s, acc[j][5] * s, acc[j][6] * s, acc[j][7] * s);
        }
    }
}

// ---------------------------------------------------------------------------
// Gather-aggregate per dst node (no atomics), fused epilogue:
//   out[n] = act( rsi[n] * sum_{s in seg(n)} A[s] + bias )
template <bool RELU>
__global__ void k_agg(const float* __restrict__ Asrc, const float* __restrict__ bias,
                      float* __restrict__ out) {
    int idx = blockIdx.x * blockDim.x + threadIdx.x;
    if (idx >= N_NODES * 16) return;
    int node = idx >> 4;
    int c = idx & 15;

    int base = g_off[node];
    int deg  = g_degi[node];
    int end  = base + deg;

    const float4* A = (const float4*)Asrc;
    float4 acc = make_float4(0.f, 0.f, 0.f, 0.f);

    int i = base;
    for (; i + 4 <= end; i += 4) {
        int s0 = __ldg(g_sorted + i);
        int s1 = __ldg(g_sorted + i + 1);
        int s2 = __ldg(g_sorted + i + 2);
        int s3 = __ldg(g_sorted + i + 3);
        float4 v0 = __ldg(A + (size_t)s0 * 16 + c);
        float4 v1 = __ldg(A + (size_t)s1 * 16 + c);
        float4 v2 = __ldg(A + (size_t)s2 * 16 + c);
        float4 v3 = __ldg(A + (size_t)s3 * 16 + c);
        acc.x += (v0.x + v1.x) + (v2.x + v3.x);
        acc.y += (v0.y + v1.y) + (v2.y + v3.y);
        acc.z += (v0.z + v1.z) + (v2.z + v3.z);
        acc.w += (v0.w + v1.w) + (v2.w + v3.w);
    }
    for (; i < end; ++i) {
        int s = __ldg(g_sorted + i);
        float4 v = __ldg(A + (size_t)s * 16 + c);
        acc.x += v.x; acc.y += v.y; acc.z += v.z; acc.w += v.w;
    }

    float sc = g_rsi[node];
    float4 bb = __ldg(((const float4*)bias) + c);
    float4 o;
    o.x = acc.x * sc + bb.x;
    o.y = acc.y * sc + bb.y;
    o.z = acc.z * sc + bb.z;
    o.w = acc.w * sc + bb.w;
    if (RELU) {
        o.x = fmaxf(o.x, 0.f); o.y = fmaxf(o.y, 0.f);
        o.z = fmaxf(o.z, 0.f); o.w = fmaxf(o.w, 0.f);
    }
    ((float4*)out)[idx] = o;
}

// ---------------------------------------------------------------------------
extern "C" void kernel_launch(void* const* d_in, const int* in_sizes, int n_in,
                              void* d_out, int out_size) {
    const float* x   = (const float*)d_in[0];
    const int*   src = (const int*)  d_in[1];
    const int*   dst = (const int*)  d_in[2];
    const float* W1  = (const float*)d_in[3];
    const float* b1  = (const float*)d_in[4];
    const float* W2  = (const float*)d_in[5];
    const float* b2  = (const float*)d_in[6];
    float* out = (float*)d_out;

    const int E = in_sizes[1];
    const int M = in_sizes[0] / F1;  // == N_NODES

    void* pA = nullptr; void* pC = nullptr;
    cudaGetSymbolAddress(&pA, g_bufA);
    cudaGetSymbolAddress(&pC, g_bufC);

    const int T = 256;
    const int smem1 = (F1 * 16 + 128 * (F1 / 4)) * 16;  // 96 KB
    const int smem2 = (F2 * 16 + 128 * (F2 / 4)) * 16;  // 48 KB
    cudaFuncSetAttribute(k_gemm_scale<F1>, cudaFuncAttributeMaxDynamicSharedMemorySize, smem1);
    cudaFuncSetAttribute(k_gemm_scale<F2>, cudaFuncAttributeMaxDynamicSharedMemorySize, smem2);

    // 1) zero int degrees + allocator
    k_zero<<<(N_NODES + T - 1) / T, T>>>();
    // 2) integer degrees
    k_degree<<<(E + T - 1) / T, T>>>(src, dst, E);
    // 3) per-node segment allocation + rsqrt norms (fused)
    k_alloc<<<(N_NODES + T - 1) / T, T>>>();
    // 4) group src indices by dst (counting sort placement)
    k_bin<<<(E + T - 1) / T, T>>>(src, dst, E);
    // 5) layer 1 GEMM first (64-wide messages): A = (x @ W1) * rso
    k_gemm_scale<F1><<<(M + 127) / 128, 128, smem1>>>(x, W1, (float*)pA, M);
    // 6) gather-aggregate + epilogue: h1 = relu(rsi * sum A[srcs] + b1)
    k_agg<true><<<(N_NODES * 16 + T - 1) / T, T>>>((const float*)pA, b1, (float*)pC);
    // 7) layer 2 GEMM: A = (h1 @ W2) * rso
    k_gemm_scale<F2><<<(M + 127) / 128, 128, smem2>>>((const float*)pC, W2, (float*)pA, M);
    // 8) gather-aggregate + epilogue: out = rsi * sum A[srcs] + b2
    k_agg<false><<<(N_NODES * 16 + T - 1) / T, T>>>((const float*)pA, b2, out);
}

// round 13
// speedup vs baseline: 1.1525x; 1.1525x over previous
#include <cuda_runtime.h>
#include <cuda_bf16.h>
#include <cstdint>

#define N_NODES 100000
#define F1 128
#define F2 64
#define EMAX 1600000

// Scratch (device globals: allocation-free, graph-safe)
__device__ float g_bufA[N_NODES * F2];   // GEMM output (pre-aggregation messages)
__device__ float g_bufC[N_NODES * F2];   // hidden activations h1
__device__ float g_rso[N_NODES];         // rsqrt(deg_out)
__device__ float g_rsi[N_NODES];         // rsqrt(deg_in)
__device__ int   g_dego[N_NODES];
__device__ int   g_degi[N_NODES];
__device__ int   g_off[N_NODES];         // segment start per dst node
__device__ int   g_cur[N_NODES];         // fill cursor per dst node
__device__ int   g_sorted[EMAX];         // src indices grouped by dst
__device__ int   g_total;                // segment allocator

// ---------------------------------------------------------------------------
__global__ void k_zero() {
    int i = blockIdx.x * blockDim.x + threadIdx.x;
    if (i < N_NODES) { g_dego[i] = 0; g_degi[i] = 0; }
    if (i == 0) g_total = 0;
}

__global__ void k_degree(const int* __restrict__ src, const int* __restrict__ dst, int E) {
    int i = blockIdx.x * blockDim.x + threadIdx.x;
    if (i >= E) return;
    atomicAdd(&g_dego[src[i]], 1);
    atomicAdd(&g_degi[dst[i]], 1);
}

// Segment allocation (warp scan + 1 atomic/warp) fused with norm computation.
__global__ void k_alloc() {
    int i = blockIdx.x * blockDim.x + threadIdx.x;
    int lane = threadIdx.x & 31;
    int deg = 0, dego = 0;
    if (i < N_NODES) { deg = g_degi[i]; dego = g_dego[i]; }
    int incl = deg;
#pragma unroll
    for (int o = 1; o < 32; o <<= 1) {
        int n = __shfl_up_sync(0xFFFFFFFFu, incl, o);
        if (lane >= o) incl += n;
    }
    int wtotal = __shfl_sync(0xFFFFFFFFu, incl, 31);
    int base = 0;
    if (lane == 0) base = atomicAdd(&g_total, wtotal);
    base = __shfl_sync(0xFFFFFFFFu, base, 0);
    if (i < N_NODES) {
        int off = base + incl - deg;
        g_off[i] = off;
        g_cur[i] = off;
        g_rsi[i] = rsqrtf((float)max(deg, 1));
        g_rso[i] = rsqrtf((float)max(dego, 1));
    }
}

// Group src indices by dst (counting-sort placement).
__global__ void k_bin(const int* __restrict__ src, const int* __restrict__ dst, int E) {
    int e = blockIdx.x * blockDim.x + threadIdx.x;
    if (e >= E) return;
    int d = dst[e];
    int p = atomicAdd(&g_cur[d], 1);
    g_sorted[p] = src[e];
}

// ---------------------------------------------------------------------------
// Y[r, :] = (X[r, :] @ W) * (SCALE ? g_rso[r] : 1)   X:[M,K] W:[K,64] Y:[M,64]
// R3's known-best config: 64-row tile, 256 threads, 4x4 register blocking.
template <int K, bool SCALE>
__global__ void k_gemm_scale(const float* __restrict__ X, const float* __restrict__ W,
                             float* __restrict__ Y, int M) {
    extern __shared__ float smem[];
    float* sW = smem;            // [K][64]
    float* sX = smem + K * 64;   // [64][K]

    const int tid = threadIdx.x;
    const int row0 = blockIdx.x * 64;

    for (int i = tid; i < K * 64 / 4; i += 256)
        ((float4*)sW)[i] = ((const float4*)W)[i];

    const int RV = K / 4;
    for (int i = tid; i < 64 * RV; i += 256) {
        int r = i / RV, c = i % RV;
        float4 v = make_float4(0.f, 0.f, 0.f, 0.f);
        if (row0 + r < M)
            v = ((const float4*)(X + (size_t)(row0 + r) * K))[c];
        ((float4*)sX)[i] = v;
    }
    __syncthreads();

    const int tx = tid & 15;
    const int ty = tid >> 4;

    float acc[4][4];
#pragma unroll
    for (int j = 0; j < 4; j++)
#pragma unroll
        for (int c = 0; c < 4; c++) acc[j][c] = 0.0f;

    for (int k4 = 0; k4 < K / 4; ++k4) {
        float4 xv[4];
#pragma unroll
        for (int j = 0; j < 4; j++)
            xv[j] = ((const float4*)(sX + (ty * 4 + j) * K))[k4];
#pragma unroll
        for (int kk = 0; kk < 4; kk++) {
            float4 wv = ((const float4*)(sW + (k4 * 4 + kk) * 64))[tx];
#pragma unroll
            for (int j = 0; j < 4; j++) {
                const float* xp = (const float*)&xv[j];
                float xs = xp[kk];
                acc[j][0] += xs * wv.x;
                acc[j][1] += xs * wv.y;
                acc[j][2] += xs * wv.z;
                acc[j][3] += xs * wv.w;
            }
        }
    }

#pragma unroll
    for (int j = 0; j < 4; j++) {
        int gr = row0 + ty * 4 + j;
        if (gr < M) {
            float s = SCALE ? g_rso[gr] : 1.0f;
            float4 o = make_float4(acc[j][0] * s, acc[j][1] * s, acc[j][2] * s, acc[j][3] * s);
            ((float4*)(Y + (size_t)gr * 64))[tx] = o;
        }
    }
}

// ---------------------------------------------------------------------------
// Gather-aggregate per dst node (no atomics), fused epilogue:
//   out[n] = act( rsi[n] * sum_{s in seg(n)} (RSO ? rso[s] : 1) * A[s] + bias )
template <bool RELU, bool RSO>
__global__ void k_agg(const float* __restrict__ Asrc, const float* __restrict__ bias,
                      float* __restrict__ out) {
    int idx = blockIdx.x * blockDim.x + threadIdx.x;
    if (idx >= N_NODES * 16) return;
    int node = idx >> 4;
    int c = idx & 15;

    int base = g_off[node];
    int deg  = g_degi[node];
    int end  = base + deg;

    const float4* A = (const float4*)Asrc;
    float4 acc = make_float4(0.f, 0.f, 0.f, 0.f);

    int i = base;
    for (; i + 4 <= end; i += 4) {
        int s0 = __ldg(g_sorted + i);
        int s1 = __ldg(g_sorted + i + 1);
        int s2 = __ldg(g_sorted + i + 2);
        int s3 = __ldg(g_sorted + i + 3);
        float4 v0 = __ldg(A + (size_t)s0 * 16 + c);
        float4 v1 = __ldg(A + (size_t)s1 * 16 + c);
        float4 v2 = __ldg(A + (size_t)s2 * 16 + c);
        float4 v3 = __ldg(A + (size_t)s3 * 16 + c);
        if (RSO) {
            float r0 = __ldg(g_rso + s0), r1 = __ldg(g_rso + s1);
            float r2 = __ldg(g_rso + s2), r3 = __ldg(g_rso + s3);
            acc.x += (v0.x * r0 + v1.x * r1) + (v2.x * r2 + v3.x * r3);
            acc.y += (v0.y * r0 + v1.y * r1) + (v2.y * r2 + v3.y * r3);
            acc.z += (v0.z * r0 + v1.z * r1) + (v2.z * r2 + v3.z * r3);
            acc.w += (v0.w * r0 + v1.w * r1) + (v2.w * r2 + v3.w * r3);
        } else {
            acc.x += (v0.x + v1.x) + (v2.x + v3.x);
            acc.y += (v0.y + v1.y) + (v2.y + v3.y);
            acc.z += (v0.z + v1.z) + (v2.z + v3.z);
            acc.w += (v0.w + v1.w) + (v2.w + v3.w);
        }
    }
    for (; i < end; ++i) {
        int s = __ldg(g_sorted + i);
        float4 v = __ldg(A + (size_t)s * 16 + c);
        float r = RSO ? __ldg(g_rso + s) : 1.0f;
        acc.x += v.x * r; acc.y += v.y * r; acc.z += v.z * r; acc.w += v.w * r;
    }

    float sc = g_rsi[node];
    float4 bb = __ldg(((const float4*)bias) + c);
    float4 o;
    o.x = acc.x * sc + bb.x;
    o.y = acc.y * sc + bb.y;
    o.z = acc.z * sc + bb.z;
    o.w = acc.w * sc + bb.w;
    if (RELU) {
        o.x = fmaxf(o.x, 0.f); o.y = fmaxf(o.y, 0.f);
        o.z = fmaxf(o.z, 0.f); o.w = fmaxf(o.w, 0.f);
    }
    ((float4*)out)[idx] = o;
}

// ---------------------------------------------------------------------------
extern "C" void kernel_launch(void* const* d_in, const int* in_sizes, int n_in,
                              void* d_out, int out_size) {
    const float* x   = (const float*)d_in[0];
    const int*   src = (const int*)  d_in[1];
    const int*   dst = (const int*)  d_in[2];
    const float* W1  = (const float*)d_in[3];
    const float* b1  = (const float*)d_in[4];
    const float* W2  = (const float*)d_in[5];
    const float* b2  = (const float*)d_in[6];
    float* out = (float*)d_out;

    const int E = in_sizes[1];
    const int M = in_sizes[0] / F1;  // == N_NODES

    void* pA = nullptr; void* pC = nullptr;
    cudaGetSymbolAddress(&pA, g_bufA);
    cudaGetSymbolAddress(&pC, g_bufC);

    // Side stream + events for fork/join (created once on first, non-captured
    // call; no device memory involved).
    static cudaStream_t s2 = nullptr;
    static cudaEvent_t evFork = nullptr, evJoin = nullptr;
    if (!s2) {
        cudaStreamCreateWithFlags(&s2, cudaStreamNonBlocking);
        cudaEventCreateWithFlags(&evFork, cudaEventDisableTiming);
        cudaEventCreateWithFlags(&evJoin, cudaEventDisableTiming);
    }

    const int T = 256;
    const int smem1 = (F1 * 64 + 64 * F1) * 4;  // 64 KB
    const int smem2 = (F2 * 64 + 64 * F2) * 4;  // 32 KB
    cudaFuncSetAttribute((const void*)k_gemm_scale<F1, false>,
                         cudaFuncAttributeMaxDynamicSharedMemorySize, smem1);
    cudaFuncSetAttribute((const void*)k_gemm_scale<F2, true>,
                         cudaFuncAttributeMaxDynamicSharedMemorySize, smem2);

    // Fork: preprocessing chain (latency-bound) on s2, GEMM1 (compute-bound)
    // on the main stream. GEMM1 depends only on x/W1 (rso applied in agg1).
    cudaEventRecord(evFork, 0);
    cudaStreamWaitEvent(s2, evFork, 0);
    k_zero<<<(N_NODES + T - 1) / T, T, 0, s2>>>();
    k_degree<<<(E + T - 1) / T, T, 0, s2>>>(src, dst, E);
    k_alloc<<<(N_NODES + T - 1) / T, T, 0, s2>>>();
    k_bin<<<(E + T - 1) / T, T, 0, s2>>>(src, dst, E);
    cudaEventRecord(evJoin, s2);

    // Main stream: layer-1 GEMM (unscaled): A = x @ W1
    k_gemm_scale<F1, false><<<(M + 63) / 64, 256, smem1>>>(x, W1, (float*)pA, M);

    // Join: aggregation needs both GEMM1 and the bin structure.
    cudaStreamWaitEvent(0, evJoin, 0);

    // h1 = relu(rsi * sum rso[s]*A[s] + b1)
    k_agg<true, true><<<(N_NODES * 16 + T - 1) / T, T>>>((const float*)pA, b1, (float*)pC);
    // layer-2 GEMM (rso in epilogue): A = (h1 @ W2) * rso
    k_gemm_scale<F2, true><<<(M + 63) / 64, 256, smem2>>>((const float*)pC, W2, (float*)pA, M);
    // out = rsi * sum A[srcs] + b2
    k_agg<false, false><<<(N_NODES * 16 + T - 1) / T, T>>>((const float*)pA, b2, out);
}

// round 15
// speedup vs baseline: 1.2102x; 1.0500x over previous
#include <cuda_runtime.h>
#include <cuda_bf16.h>
#include <cstdint>

#define N_NODES 100000
#define F1 128
#define F2 64
#define EMAX 1600000

// Scratch (device globals: allocation-free, graph-safe)
__device__ float g_bufA[N_NODES * F2];   // GEMM output (pre-aggregation messages)
__device__ float g_bufC[N_NODES * F2];   // hidden activations h1
__device__ float g_rso[N_NODES];         // rsqrt(deg_out)
__device__ float g_rsi[N_NODES];         // rsqrt(deg_in)
__device__ int   g_dego[N_NODES];
__device__ int   g_degi[N_NODES];
__device__ int   g_off[N_NODES];         // segment start per dst node
__device__ int   g_cur[N_NODES];         // fill cursor per dst node
__device__ int   g_sorted[EMAX];         // src indices grouped by dst
__device__ int   g_total;                // segment allocator

// ---------------------------------------------------------------------------
__global__ void k_zero() {
    int i = blockIdx.x * blockDim.x + threadIdx.x;
    if (i < N_NODES) { g_dego[i] = 0; g_degi[i] = 0; }
    if (i == 0) g_total = 0;
}

__global__ void k_degree(const int* __restrict__ src, const int* __restrict__ dst, int E) {
    int i = blockIdx.x * blockDim.x + threadIdx.x;
    if (i >= E) return;
    atomicAdd(&g_dego[src[i]], 1);
    atomicAdd(&g_degi[dst[i]], 1);
}

// Segment allocation (warp scan + 1 atomic/warp) fused with norm computation.
__global__ void k_alloc() {
    int i = blockIdx.x * blockDim.x + threadIdx.x;
    int lane = threadIdx.x & 31;
    int deg = 0, dego = 0;
    if (i < N_NODES) { deg = g_degi[i]; dego = g_dego[i]; }
    int incl = deg;
#pragma unroll
    for (int o = 1; o < 32; o <<= 1) {
        int n = __shfl_up_sync(0xFFFFFFFFu, incl, o);
        if (lane >= o) incl += n;
    }
    int wtotal = __shfl_sync(0xFFFFFFFFu, incl, 31);
    int base = 0;
    if (lane == 0) base = atomicAdd(&g_total, wtotal);
    base = __shfl_sync(0xFFFFFFFFu, base, 0);
    if (i < N_NODES) {
        int off = base + incl - deg;
        g_off[i] = off;
        g_cur[i] = off;
        g_rsi[i] = rsqrtf((float)max(deg, 1));
        g_rso[i] = rsqrtf((float)max(dego, 1));
    }
}

// Group src indices by dst (counting-sort placement).
__global__ void k_bin(const int* __restrict__ src, const int* __restrict__ dst, int E) {
    int e = blockIdx.x * blockDim.x + threadIdx.x;
    if (e >= E) return;
    int d = dst[e];
    int p = atomicAdd(&g_cur[d], 1);
    g_sorted[p] = src[e];
}

// ---------------------------------------------------------------------------
// Y[r, :] = (X[r, :] @ W) * (SCALE ? g_rso[r] : 1)   X:[M,K] W:[K,64] Y:[M,64]
// R3's 4x4 blocking, but K processed in 64-wide chunks -> 32 KB static smem
// -> ~5 blocks/SM (reg-limited) instead of 3, for latency hiding.
template <int K, bool SCALE>
__global__ void __launch_bounds__(256)
k_gemm_scale(const float* __restrict__ X, const float* __restrict__ W,
             float* __restrict__ Y, int M) {
    constexpr int KC = 64;                 // k-chunk width
    constexpr int NCH = K / KC;
    __shared__ float sW[KC * 64];          // 16 KB
    __shared__ float sX[64 * KC];          // 16 KB

    const int tid = threadIdx.x;
    const int row0 = blockIdx.x * 64;
    const int tx = tid & 15;
    const int ty = tid >> 4;

    float acc[4][4];
#pragma unroll
    for (int j = 0; j < 4; j++)
#pragma unroll
        for (int c = 0; c < 4; c++) acc[j][c] = 0.0f;

#pragma unroll
    for (int ch = 0; ch < NCH; ++ch) {
        // Load W chunk: rows ch*KC .. ch*KC+KC of [K][64]
        for (int i = tid; i < KC * 16; i += 256)
            ((float4*)sW)[i] = ((const float4*)(W + ch * KC * 64))[i];

        // Load X chunk: [64][KC] (zero-fill out-of-range rows)
        for (int i = tid; i < 64 * (KC / 4); i += 256) {
            int r = i / (KC / 4), c = i % (KC / 4);
            float4 v = make_float4(0.f, 0.f, 0.f, 0.f);
            if (row0 + r < M)
                v = ((const float4*)(X + (size_t)(row0 + r) * K + ch * KC))[c];
            ((float4*)sX)[i] = v;
        }
        __syncthreads();

        for (int k4 = 0; k4 < KC / 4; ++k4) {
            float4 xv[4];
#pragma unroll
            for (int j = 0; j < 4; j++)
                xv[j] = ((const float4*)(sX + (ty * 4 + j) * KC))[k4];
#pragma unroll
            for (int kk = 0; kk < 4; kk++) {
                float4 wv = ((const float4*)(sW + (k4 * 4 + kk) * 64))[tx];
#pragma unroll
                for (int j = 0; j < 4; j++) {
                    const float* xp = (const float*)&xv[j];
                    float xs = xp[kk];
                    acc[j][0] += xs * wv.x;
                    acc[j][1] += xs * wv.y;
                    acc[j][2] += xs * wv.z;
                    acc[j][3] += xs * wv.w;
                }
            }
        }
        __syncthreads();
    }

#pragma unroll
    for (int j = 0; j < 4; j++) {
        int gr = row0 + ty * 4 + j;
        if (gr < M) {
            float s = SCALE ? g_rso[gr] : 1.0f;
            float4 o = make_float4(acc[j][0] * s, acc[j][1] * s, acc[j][2] * s, acc[j][3] * s);
            ((float4*)(Y + (size_t)gr * 64))[tx] = o;
        }
    }
}

// ---------------------------------------------------------------------------
// Gather-aggregate per dst node (no atomics), fused epilogue:
//   out[n] = act( rsi[n] * sum_{s in seg(n)} (RSO ? rso[s] : 1) * A[s] + bias )
template <bool RELU, bool RSO>
__global__ void k_agg(const float* __restrict__ Asrc, const float* __restrict__ bias,
                      float* __restrict__ out) {
    int idx = blockIdx.x * blockDim.x + threadIdx.x;
    if (idx >= N_NODES * 16) return;
    int node = idx >> 4;
    int c = idx & 15;

    int base = g_off[node];
    int deg  = g_degi[node];
    int end  = base + deg;

    const float4* A = (const float4*)Asrc;
    float4 acc = make_float4(0.f, 0.f, 0.f, 0.f);

    int i = base;
    for (; i + 4 <= end; i += 4) {
        int s0 = __ldg(g_sorted + i);
        int s1 = __ldg(g_sorted + i + 1);
        int s2 = __ldg(g_sorted + i + 2);
        int s3 = __ldg(g_sorted + i + 3);
        float4 v0 = __ldg(A + (size_t)s0 * 16 + c);
        float4 v1 = __ldg(A + (size_t)s1 * 16 + c);
        float4 v2 = __ldg(A + (size_t)s2 * 16 + c);
        float4 v3 = __ldg(A + (size_t)s3 * 16 + c);
        if (RSO) {
            float r0 = __ldg(g_rso + s0), r1 = __ldg(g_rso + s1);
            float r2 = __ldg(g_rso + s2), r3 = __ldg(g_rso + s3);
            acc.x += (v0.x * r0 + v1.x * r1) + (v2.x * r2 + v3.x * r3);
            acc.y += (v0.y * r0 + v1.y * r1) + (v2.y * r2 + v3.y * r3);
            acc.z += (v0.z * r0 + v1.z * r1) + (v2.z * r2 + v3.z * r3);
            acc.w += (v0.w * r0 + v1.w * r1) + (v2.w * r2 + v3.w * r3);
        } else {
            acc.x += (v0.x + v1.x) + (v2.x + v3.x);
            acc.y += (v0.y + v1.y) + (v2.y + v3.y);
            acc.z += (v0.z + v1.z) + (v2.z + v3.z);
            acc.w += (v0.w + v1.w) + (v2.w + v3.w);
        }
    }
    for (; i < end; ++i) {
        int s = __ldg(g_sorted + i);
        float4 v = __ldg(A + (size_t)s * 16 + c);
        float r = RSO ? __ldg(g_rso + s) : 1.0f;
        acc.x += v.x * r; acc.y += v.y * r; acc.z += v.z * r; acc.w += v.w * r;
    }

    float sc = g_rsi[node];
    float4 bb = __ldg(((const float4*)bias) + c);
    float4 o;
    o.x = acc.x * sc + bb.x;
    o.y = acc.y * sc + bb.y;
    o.z = acc.z * sc + bb.z;
    o.w = acc.w * sc + bb.w;
    if (RELU) {
        o.x = fmaxf(o.x, 0.f); o.y = fmaxf(o.y, 0.f);
        o.z = fmaxf(o.z, 0.f); o.w = fmaxf(o.w, 0.f);
    }
    ((float4*)out)[idx] = o;
}

// ---------------------------------------------------------------------------
extern "C" void kernel_launch(void* const* d_in, const int* in_sizes, int n_in,
                              void* d_out, int out_size) {
    const float* x   = (const float*)d_in[0];
    const int*   src = (const int*)  d_in[1];
    const int*   dst = (const int*)  d_in[2];
    const float* W1  = (const float*)d_in[3];
    const float* b1  = (const float*)d_in[4];
    const float* W2  = (const float*)d_in[5];
    const float* b2  = (const float*)d_in[6];
    float* out = (float*)d_out;

    const int E = in_sizes[1];
    const int M = in_sizes[0] / F1;  // == N_NODES

    void* pA = nullptr; void* pC = nullptr;
    cudaGetSymbolAddress(&pA, g_bufA);
    cudaGetSymbolAddress(&pC, g_bufC);

    // Side stream + events for fork/join (created once on first, non-captured
    // call; no device memory involved).
    static cudaStream_t s2 = nullptr;
    static cudaEvent_t evFork = nullptr, evJoin = nullptr;
    if (!s2) {
        cudaStreamCreateWithFlags(&s2, cudaStreamNonBlocking);
        cudaEventCreateWithFlags(&evFork, cudaEventDisableTiming);
        cudaEventCreateWithFlags(&evJoin, cudaEventDisableTiming);
    }

    const int T = 256;

    // Fork: preprocessing chain (latency-bound) on s2, GEMM1 (compute-bound)
    // on the main stream. GEMM1 depends only on x/W1 (rso applied in agg1).
    cudaEventRecord(evFork, 0);
    cudaStreamWaitEvent(s2, evFork, 0);
    k_zero<<<(N_NODES + T - 1) / T, T, 0, s2>>>();
    k_degree<<<(E + T - 1) / T, T, 0, s2>>>(src, dst, E);
    k_alloc<<<(N_NODES + T - 1) / T, T, 0, s2>>>();
    k_bin<<<(E + T - 1) / T, T, 0, s2>>>(src, dst, E);
    cudaEventRecord(evJoin, s2);

    // Main stream: layer-1 GEMM (unscaled): A = x @ W1
    k_gemm_scale<F1, false><<<(M + 63) / 64, 256>>>(x, W1, (float*)pA, M);

    // Join: aggregation needs both GEMM1 and the bin structure.
    cudaStreamWaitEvent(0, evJoin, 0);

    // h1 = relu(rsi * sum rso[s]*A[s] + b1)
    k_agg<true, true><<<(N_NODES * 16 + T - 1) / T, T>>>((const float*)pA, b1, (float*)pC);
    // layer-2 GEMM (rso in epilogue): A = (h1 @ W2) * rso
    k_gemm_scale<F2, true><<<(M + 63) / 64, 256>>>((const float*)pC, W2, (float*)pA, M);
    // out = rsi * sum A[srcs] + b2
    k_agg<false, false><<<(N_NODES * 16 + T - 1) / T, T>>>((const float*)pA, b2, out);
}